// round 2
// baseline (speedup 1.0000x reference)
#include <cuda_runtime.h>
#include <math.h>

// Problem dims
#define BB    32
#define TENC  1024
#define ENCD  1024
#define DECD  1024
#define MELD  80
// Attention split
#define NC    32          // chunks over T
#define CT    32          // timesteps per chunk
// LSTM GEMM
#define KTOT  2128        // 80 (mel) + 1024 (ctx) + 1024 (h)
#define TK    16
#define NTILES 133        // 2128/16
#define KSPLIT 7
#define TPS    19         // 133/7

// Output layout: [mel(32*80), h_new(32*1024), c_new(32*1024)]
#define OFF_MEL 0
#define OFF_H   (BB*MELD)
#define OFF_C   (BB*MELD + BB*DECD)

// Scratch (static device memory — no allocations allowed)
__device__ float g_m[BB*NC];
__device__ float g_l[BB*NC];
__device__ float g_acc[BB*NC*ENCD];
__device__ float g_ctx[BB*ENCD];
__device__ float g_zp[KSPLIT*BB*4*DECD];

#define LOG2E 1.4426950408889634f

__device__ __forceinline__ float fast_tanh(float x) {
    // tanh(x) = 1 - 2/(exp(2x)+1); exp via MUFU.EX2. |x| never near overflow here.
    float u = exp2f(x * (2.0f * LOG2E));
    return 1.0f - __fdividef(2.0f, u + 1.0f);
}
__device__ __forceinline__ float fast_sig(float x) {
    return __fdividef(1.0f, 1.0f + exp2f(-LOG2E * x));
}

// ---------------------------------------------------------------------------
// Kernel A: online-softmax attention partials. Grid (B, NC), 128 threads.
// Each warp handles 8 timesteps; per-lane acc[k] covers d = lane + 32k.
// Reads enc exactly once (128 MB total).
// ---------------------------------------------------------------------------
__global__ void __launch_bounds__(128) attn_partial(
    const float* __restrict__ enc, const float* __restrict__ h,
    const float* __restrict__ scale)
{
    const int b = blockIdx.x, c = blockIdx.y;
    const int wid = threadIdx.x >> 5, lane = threadIdx.x & 31;

    float hs[32], sc[32], acc[32];
    #pragma unroll
    for (int k = 0; k < 32; k++) {
        hs[k]  = h[b*DECD + lane + 32*k];
        sc[k]  = scale[lane + 32*k];
        acc[k] = 0.0f;
    }
    float m = -INFINITY, l = 0.0f;

    const int t0 = c*CT + wid*8;
    for (int i = 0; i < 8; i++) {
        const int t = t0 + i;
        const float* ep = enc + ((long)(b*TENC + t))*ENCD + lane;
        float e[32];
        float s = 0.0f;
        #pragma unroll
        for (int k = 0; k < 32; k++) {
            e[k] = ep[32*k];
            float x  = hs[k] + e[k];
            float u  = exp2f(x * (2.0f * LOG2E));
            float th = 1.0f - __fdividef(2.0f, u + 1.0f);
            s = fmaf(sc[k], th, s);
        }
        #pragma unroll
        for (int off = 16; off > 0; off >>= 1)
            s += __shfl_xor_sync(0xffffffffu, s, off);

        if (s > m) {  // warp-uniform branch (s is fully reduced)
            float alpha = exp2f((m - s) * LOG2E);   // exp2(-inf)=0 on first t
            l = fmaf(l, alpha, 1.0f);
            m = s;
            #pragma unroll
            for (int k = 0; k < 32; k++)
                acc[k] = fmaf(acc[k], alpha, e[k]);
        } else {
            float w = exp2f((s - m) * LOG2E);
            l += w;
            #pragma unroll
            for (int k = 0; k < 32; k++)
                acc[k] = fmaf(w, e[k], acc[k]);
        }
    }

    // Block combine across the 4 warps
    __shared__ float sm_m[4], sm_l[4];
    __shared__ float sacc[4][ENCD];
    #pragma unroll
    for (int k = 0; k < 32; k++)
        sacc[wid][32*k + lane] = acc[k];
    if (lane == 0) { sm_m[wid] = m; sm_l[wid] = l; }
    __syncthreads();

    float mb = fmaxf(fmaxf(sm_m[0], sm_m[1]), fmaxf(sm_m[2], sm_m[3]));
    float f0 = exp2f((sm_m[0]-mb)*LOG2E), f1 = exp2f((sm_m[1]-mb)*LOG2E);
    float f2 = exp2f((sm_m[2]-mb)*LOG2E), f3 = exp2f((sm_m[3]-mb)*LOG2E);
    float lb = sm_l[0]*f0 + sm_l[1]*f1 + sm_l[2]*f2 + sm_l[3]*f3;

    for (int d = threadIdx.x; d < ENCD; d += 128) {
        float v = sacc[0][d]*f0 + sacc[1][d]*f1 + sacc[2][d]*f2 + sacc[3][d]*f3;
        g_acc[(b*NC + c)*ENCD + d] = v;
    }
    if (threadIdx.x == 0) { g_m[b*NC + c] = mb; g_l[b*NC + c] = lb; }
}

// ---------------------------------------------------------------------------
// Kernel B: combine chunk partials -> context. Grid (B), 256 threads.
// ---------------------------------------------------------------------------
__global__ void __launch_bounds__(256) attn_combine()
{
    const int b = blockIdx.x, tid = threadIdx.x;
    __shared__ float sm[NC], sl[NC], sf[NC];
    if (tid < NC) { sm[tid] = g_m[b*NC + tid]; sl[tid] = g_l[b*NC + tid]; }
    __syncthreads();
    float M = -INFINITY;
    #pragma unroll
    for (int c = 0; c < NC; c++) M = fmaxf(M, sm[c]);
    if (tid < NC) sf[tid] = exp2f((sm[tid] - M) * LOG2E);
    __syncthreads();
    float L = 0.0f;
    #pragma unroll
    for (int c = 0; c < NC; c++) L += sl[c] * sf[c];
    float invL = __fdividef(1.0f, L);

    for (int d = tid; d < ENCD; d += 256) {
        float v = 0.0f;
        #pragma unroll 8
        for (int c = 0; c < NC; c++)
            v = fmaf(g_acc[(b*NC + c)*ENCD + d], sf[c], v);
        g_ctx[b*ENCD + d] = v * invL;
    }
}

// ---------------------------------------------------------------------------
// Kernel C: z partials = x@Wk + h@Wr. Grid (32 j-blocks, KSPLIT), 128 threads.
// Thread owns one column j, 32 per-batch accumulators. x staged in smem,
// read back as float2 broadcasts.
// ---------------------------------------------------------------------------
__global__ void __launch_bounds__(128) lstm_gemm(
    const float* __restrict__ pm, const float* __restrict__ h,
    const float* __restrict__ Wk, const float* __restrict__ Wr)
{
    const int tid = threadIdx.x;
    const int j   = blockIdx.x * 128 + tid;
    const int ks  = blockIdx.y;

    float acc[32];
    #pragma unroll
    for (int b = 0; b < 32; b++) acc[b] = 0.0f;

    __shared__ __align__(16) float xs[TK * 34];   // xs[kk*34 + b]

    const int tile0 = ks * TPS;
    for (int tile = tile0; tile < tile0 + TPS; tile++) {
        const int kbase = tile * TK;
        __syncthreads();
        #pragma unroll
        for (int i = 0; i < 4; i++) {
            int idx = tid + 128*i;        // [0,512)
            int b   = idx >> 4;
            int kk  = idx & 15;
            int k   = kbase + kk;
            float v;
            if (k < MELD)            v = pm[b*MELD + k];
            else if (k < MELD+ENCD)  v = g_ctx[b*ENCD + (k - MELD)];
            else                     v = h[b*DECD + (k - MELD - ENCD)];
            xs[kk*34 + b] = v;
        }
        __syncthreads();

        const float* wrow = (tile < 69)
            ? (Wk + (long)kbase*4096 + j)
            : (Wr + (long)(kbase - (MELD+ENCD))*4096 + j);

        #pragma unroll
        for (int kk = 0; kk < TK; kk++) {
            float w = wrow[kk*4096];
            const float2* xp = reinterpret_cast<const float2*>(xs + kk*34);
            #pragma unroll
            for (int bb = 0; bb < 16; bb++) {
                float2 xv = xp[bb];
                acc[2*bb]   = fmaf(xv.x, w, acc[2*bb]);
                acc[2*bb+1] = fmaf(xv.y, w, acc[2*bb+1]);
            }
        }
    }
    #pragma unroll
    for (int b = 0; b < 32; b++)
        g_zp[(ks*32 + b)*4*DECD + j] = acc[b];
}

// ---------------------------------------------------------------------------
// Kernel D: sum K-split partials + bias, gates, write h_new/c_new.
// Grid 128 x 256 threads -> 32768 = B*DEC elements.
// ---------------------------------------------------------------------------
__global__ void __launch_bounds__(256) lstm_gates(
    const float* __restrict__ c_in, const float* __restrict__ bias,
    float* __restrict__ out)
{
    const int idx = blockIdx.x*256 + threadIdx.x;   // [0, 32768)
    const int b = idx >> 10, jj = idx & 1023;

    float zi = bias[jj], zf = bias[DECD + jj];
    float zg = bias[2*DECD + jj], zo = bias[3*DECD + jj];
    #pragma unroll
    for (int ks = 0; ks < KSPLIT; ks++) {
        const float* zp = g_zp + (ks*32 + b)*4*DECD;
        zi += zp[jj];
        zf += zp[DECD + jj];
        zg += zp[2*DECD + jj];
        zo += zp[3*DECD + jj];
    }
    float ig = fast_sig(zi), fg = fast_sig(zf), og = fast_sig(zo);
    float gg = fast_tanh(zg);
    float cn = fmaf(fg, c_in[idx], ig * gg);
    float hn = og * fast_tanh(cn);
    out[OFF_H + idx] = hn;
    out[OFF_C + idx] = cn;
}

// ---------------------------------------------------------------------------
// Kernel E: mel projection. Grid (B), 96 threads (80 active).
// ---------------------------------------------------------------------------
__global__ void __launch_bounds__(96) mel_proj(
    const float* __restrict__ pw, const float* __restrict__ pb,
    float* __restrict__ out)
{
    const int b = blockIdx.x, j = threadIdx.x;
    if (j >= MELD) return;
    const float* hn = out + OFF_H + b*DECD;
    float a0 = 0.f, a1 = 0.f, a2 = 0.f, a3 = 0.f;
    for (int k = 0; k < DECD; k += 4) {
        a0 = fmaf(hn[k  ], pw[(k  )*MELD + j], a0);
        a1 = fmaf(hn[k+1], pw[(k+1)*MELD + j], a1);
        a2 = fmaf(hn[k+2], pw[(k+2)*MELD + j], a2);
        a3 = fmaf(hn[k+3], pw[(k+3)*MELD + j], a3);
    }
    out[OFF_MEL + b*MELD + j] = (a0 + a1) + (a2 + a3) + pb[j];
}

// ---------------------------------------------------------------------------
extern "C" void kernel_launch(void* const* d_in, const int* in_sizes, int n_in,
                              void* d_out, int out_size)
{
    const float* pm    = (const float*)d_in[0];  // prev_mel_frame [32,80]
    const float* enc   = (const float*)d_in[1];  // encoder_outputs [32,1024,1024]
    const float* h     = (const float*)d_in[2];  // h [32,1024]
    const float* c     = (const float*)d_in[3];  // c [32,1024]
    const float* ascl  = (const float*)d_in[4];  // attn_scale [1024]
    const float* Wk    = (const float*)d_in[5];  // kernel [1104,4096]
    const float* Wr    = (const float*)d_in[6];  // rec_kernel [1024,4096]
    const float* bias  = (const float*)d_in[7];  // bias [4096]
    const float* pw    = (const float*)d_in[8];  // proj_w [1024,80]
    const float* pb    = (const float*)d_in[9];  // proj_b [80]
    float* out = (float*)d_out;

    dim3 gA(BB, NC);
    attn_partial<<<gA, 128>>>(enc, h, ascl);
    attn_combine<<<BB, 256>>>();
    dim3 gC(32, KSPLIT);
    lstm_gemm<<<gC, 128>>>(pm, h, Wk, Wr);
    lstm_gates<<<128, 256>>>(c, bias, out);
    mel_proj<<<BB, 96>>>(pw, pb, out);
}

// round 3
// speedup vs baseline: 1.1575x; 1.1575x over previous
#include <cuda_runtime.h>
#include <math.h>

// Problem dims
#define BB    32
#define TENC  1024
#define ENCD  1024
#define DECD  1024
#define MELD  80
// Attention split
#define NC    32          // chunks over T
#define CT    32          // timesteps per chunk
#define NSB   4           // sub-blocks per chunk (8 t each)
// LSTM GEMM
#define KTOT  2128        // 80 (mel) + 1024 (ctx) + 1024 (h)
#define TK    16
#define NTILES 133        // 2128/16
#define KSPLIT 19
#define TPS    7          // 133/19

// Output layout: [mel(32*80), h_new(32*1024), c_new(32*1024)]
#define OFF_MEL 0
#define OFF_H   (BB*MELD)
#define OFF_C   (BB*MELD + BB*DECD)

// Scratch (static device memory — no allocations allowed)
__device__ float g_m[BB*NC];
__device__ float g_l[BB*NC];
__device__ float g_acc[BB*NC*ENCD];
__device__ float g_ctx[BB*ENCD];
__device__ float g_zp[KSPLIT*BB*4*DECD];

#define LOG2E  1.4426950408889634f
#define LOG2E2 2.8853900817779268f

__device__ __forceinline__ float fast_tanh(float x) {
    float u = exp2f(x * LOG2E2);
    return 1.0f - __fdividef(2.0f, u + 1.0f);
}
__device__ __forceinline__ float fast_sig(float x) {
    return __fdividef(1.0f, 1.0f + exp2f(-LOG2E * x));
}

// f32x2 packed FMA helpers (sm_103a; ptxas never emits FFMA2 from C++)
typedef unsigned long long u64t;
__device__ __forceinline__ u64t pack2(float w) {
    u64t r; asm("mov.b64 %0, {%1, %1};" : "=l"(r) : "f"(w)); return r;
}
__device__ __forceinline__ void fma2(u64t& a, u64t x, u64t w) {
    asm("fma.rn.f32x2 %0, %1, %2, %0;" : "+l"(a) : "l"(x), "l"(w));
}
__device__ __forceinline__ float2 unpack2(u64t a) {
    float2 f; asm("mov.b64 {%0, %1}, %2;" : "=f"(f.x), "=f"(f.y) : "l"(a)); return f;
}

// ---------------------------------------------------------------------------
// Kernel A: attention chunk partials, two-phase sub-block online softmax.
// Grid (B, NC), 256 threads (8 warps).
// Phase A (per sub-block of 8 t): warp w computes the score of t = sb*8+w.
// Merge: warp 0 lanes 0..7 fold the 8 scores into running (m,l), weights smem.
// Phase B: warp w owns D-slice [128w,128w+128), accumulates one float4/lane.
// enc read from DRAM once (phase A); phase B re-read hits L2 (small window).
// ---------------------------------------------------------------------------
__global__ void __launch_bounds__(256) attn_partial(
    const float* __restrict__ enc, const float* __restrict__ h,
    const float* __restrict__ scale)
{
    const int b = blockIdx.x, c = blockIdx.y;
    const int tid = threadIdx.x;
    const int wid = tid >> 5, lane = tid & 31;

    // Phase-A per-lane slices: d4 = lane + 32k  (float4 granules), k=0..7
    float4 hs[8], sc[8];
    const float4* h4 = (const float4*)(h + b*DECD);
    const float4* s4 = (const float4*)scale;
    #pragma unroll
    for (int k = 0; k < 8; k++) { hs[k] = h4[lane + 32*k]; sc[k] = s4[lane + 32*k]; }

    __shared__ float s_sm[8];
    __shared__ float w_sm[8];
    __shared__ float alpha_sm;
    __shared__ float m_sm, l_sm;
    if (tid == 0) { m_sm = -INFINITY; l_sm = 0.0f; }

    float4 acc = make_float4(0.f, 0.f, 0.f, 0.f);

    const float* encb = enc + ((long)(b*TENC) + c*CT)*ENCD;
    // Phase-B base: warp wid covers d = wid*128 + lane*4 + {0..3}
    const float4* eB = (const float4*)encb + wid*32 + lane;

    #pragma unroll 1
    for (int sb = 0; sb < NSB; sb++) {
        // ---- Phase A: score of t = sb*8 + wid ----
        const float4* eA = (const float4*)(encb + (sb*8 + wid)*ENCD) + lane;
        float p0 = 0.f, p1 = 0.f, p2 = 0.f, p3 = 0.f;
        #pragma unroll
        for (int k = 0; k < 8; k++) {
            float4 e = eA[32*k];
            p0 = fmaf(sc[k].x, fast_tanh(hs[k].x + e.x), p0);
            p1 = fmaf(sc[k].y, fast_tanh(hs[k].y + e.y), p1);
            p2 = fmaf(sc[k].z, fast_tanh(hs[k].z + e.z), p2);
            p3 = fmaf(sc[k].w, fast_tanh(hs[k].w + e.w), p3);
        }
        float s = (p0 + p1) + (p2 + p3);
        #pragma unroll
        for (int off = 16; off > 0; off >>= 1)
            s += __shfl_xor_sync(0xffffffffu, s, off);

        __syncthreads();           // prev phase B done (w_sm free); init visible
        if (lane == 0) s_sm[wid] = s;
        __syncthreads();

        // ---- Merge: warp 0, lanes 0..7 ----
        if (wid == 0 && lane < 8) {
            float sj = s_sm[lane];
            float m8 = sj;
            m8 = fmaxf(m8, __shfl_xor_sync(0xffu, m8, 1));
            m8 = fmaxf(m8, __shfl_xor_sync(0xffu, m8, 2));
            m8 = fmaxf(m8, __shfl_xor_sync(0xffu, m8, 4));
            float m_old = m_sm;
            float m_new = fmaxf(m_old, m8);
            float alpha = exp2f((m_old - m_new) * LOG2E);   // 0 on first sb
            float wj    = exp2f((sj   - m_new) * LOG2E);
            float l8 = wj;
            l8 += __shfl_xor_sync(0xffu, l8, 1);
            l8 += __shfl_xor_sync(0xffu, l8, 2);
            l8 += __shfl_xor_sync(0xffu, l8, 4);
            w_sm[lane] = wj;
            if (lane == 0) {
                alpha_sm = alpha;
                m_sm = m_new;
                l_sm = fmaf(l_sm, alpha, l8);
            }
        }
        __syncthreads();

        // ---- Phase B: weighted accumulate over the 8 t (L2-hot) ----
        float alpha = alpha_sm;
        acc.x *= alpha; acc.y *= alpha; acc.z *= alpha; acc.w *= alpha;
        #pragma unroll
        for (int jj = 0; jj < 2; jj++) {
            float4 v0 = eB[(sb*8 + jj*4 + 0)*256];
            float4 v1 = eB[(sb*8 + jj*4 + 1)*256];
            float4 v2 = eB[(sb*8 + jj*4 + 2)*256];
            float4 v3 = eB[(sb*8 + jj*4 + 3)*256];
            float w0 = w_sm[jj*4+0], w1 = w_sm[jj*4+1];
            float w2 = w_sm[jj*4+2], w3 = w_sm[jj*4+3];
            acc.x = fmaf(w0, v0.x, acc.x); acc.y = fmaf(w0, v0.y, acc.y);
            acc.z = fmaf(w0, v0.z, acc.z); acc.w = fmaf(w0, v0.w, acc.w);
            acc.x = fmaf(w1, v1.x, acc.x); acc.y = fmaf(w1, v1.y, acc.y);
            acc.z = fmaf(w1, v1.z, acc.z); acc.w = fmaf(w1, v1.w, acc.w);
            acc.x = fmaf(w2, v2.x, acc.x); acc.y = fmaf(w2, v2.y, acc.y);
            acc.z = fmaf(w2, v2.z, acc.z); acc.w = fmaf(w2, v2.w, acc.w);
            acc.x = fmaf(w3, v3.x, acc.x); acc.y = fmaf(w3, v3.y, acc.y);
            acc.z = fmaf(w3, v3.z, acc.z); acc.w = fmaf(w3, v3.w, acc.w);
        }
    }

    // Epilogue
    float4* ga = (float4*)(g_acc + (b*NC + c)*ENCD) + wid*32 + lane;
    *ga = acc;
    if (tid == 0) { g_m[b*NC + c] = m_sm; g_l[b*NC + c] = l_sm; }
}

// ---------------------------------------------------------------------------
// Kernel B: combine chunk partials -> context. Grid (B), 256 threads.
// One float4 per thread over D.
// ---------------------------------------------------------------------------
__global__ void __launch_bounds__(256) attn_combine()
{
    const int b = blockIdx.x, tid = threadIdx.x;
    __shared__ float sm[NC], sl[NC], sf[NC];
    if (tid < NC) { sm[tid] = g_m[b*NC + tid]; sl[tid] = g_l[b*NC + tid]; }
    __syncthreads();
    float M = -INFINITY;
    #pragma unroll
    for (int c = 0; c < NC; c++) M = fmaxf(M, sm[c]);
    if (tid < NC) sf[tid] = exp2f((sm[tid] - M) * LOG2E);
    __syncthreads();
    float L = 0.0f;
    #pragma unroll
    for (int c = 0; c < NC; c++) L += sl[c] * sf[c];
    float invL = __fdividef(1.0f, L);

    const float4* ga = (const float4*)g_acc;
    float4 v = make_float4(0.f, 0.f, 0.f, 0.f);
    #pragma unroll 8
    for (int c = 0; c < NC; c++) {
        float4 a = ga[(b*NC + c)*256 + tid];
        float f = sf[c];
        v.x = fmaf(a.x, f, v.x); v.y = fmaf(a.y, f, v.y);
        v.z = fmaf(a.z, f, v.z); v.w = fmaf(a.w, f, v.w);
    }
    v.x *= invL; v.y *= invL; v.z *= invL; v.w *= invL;
    ((float4*)(g_ctx + b*ENCD))[tid] = v;
}

// ---------------------------------------------------------------------------
// Kernel C: z partials = x@Wk + h@Wr, packed f32x2 FMA.
// Grid (32 j-blocks, KSPLIT=19), 128 threads. Thread owns column j,
// 16 packed batch-pair accumulators.
// ---------------------------------------------------------------------------
__global__ void __launch_bounds__(128) lstm_gemm(
    const float* __restrict__ pm, const float* __restrict__ h,
    const float* __restrict__ Wk, const float* __restrict__ Wr)
{
    const int tid = threadIdx.x;
    const int j   = blockIdx.x * 128 + tid;
    const int ks  = blockIdx.y;

    u64t acc2[16];
    #pragma unroll
    for (int i = 0; i < 16; i++) acc2[i] = 0ull;

    __shared__ __align__(16) float xs[TK * 34];   // xs[kk*34 + b]; 34*4=136 B row, 8B-aligned pairs

    const int tile0 = ks * TPS;
    for (int tile = tile0; tile < tile0 + TPS; tile++) {
        const int kbase = tile * TK;
        __syncthreads();
        #pragma unroll
        for (int i = 0; i < 4; i++) {
            int idx = tid + 128*i;        // [0,512)
            int bb  = idx >> 4;
            int kk  = idx & 15;
            int k   = kbase + kk;
            float v;
            if (k < MELD)            v = pm[bb*MELD + k];
            else if (k < MELD+ENCD)  v = g_ctx[bb*ENCD + (k - MELD)];
            else                     v = h[bb*DECD + (k - MELD - ENCD)];
            xs[kk*34 + bb] = v;
        }
        __syncthreads();

        const float* wrow = (tile < 69)
            ? (Wk + (long)kbase*4096 + j)
            : (Wr + (long)(kbase - (MELD+ENCD))*4096 + j);

        #pragma unroll
        for (int kk = 0; kk < TK; kk++) {
            u64t w2 = pack2(wrow[kk*4096]);
            const u64t* xp = reinterpret_cast<const u64t*>(xs + kk*34);
            #pragma unroll
            for (int bb = 0; bb < 16; bb++)
                fma2(acc2[bb], xp[bb], w2);
        }
    }
    #pragma unroll
    for (int bb = 0; bb < 16; bb++) {
        float2 f = unpack2(acc2[bb]);
        g_zp[(ks*32 + 2*bb  )*4*DECD + j] = f.x;
        g_zp[(ks*32 + 2*bb+1)*4*DECD + j] = f.y;
    }
}

// ---------------------------------------------------------------------------
// Kernel D: sum K-split partials + bias, gates, write h_new/c_new.
// Grid 256 x 128 threads -> 32768 = B*DEC elements.
// ---------------------------------------------------------------------------
__global__ void __launch_bounds__(128) lstm_gates(
    const float* __restrict__ c_in, const float* __restrict__ bias,
    float* __restrict__ out)
{
    const int idx = blockIdx.x*128 + threadIdx.x;   // [0, 32768)
    const int b = idx >> 10, jj = idx & 1023;

    float zi = bias[jj], zf = bias[DECD + jj];
    float zg = bias[2*DECD + jj], zo = bias[3*DECD + jj];
    #pragma unroll
    for (int ks = 0; ks < KSPLIT; ks++) {
        const float* zp = g_zp + (ks*32 + b)*4*DECD;
        zi += zp[jj];
        zf += zp[DECD + jj];
        zg += zp[2*DECD + jj];
        zo += zp[3*DECD + jj];
    }
    float ig = fast_sig(zi), fg = fast_sig(zf), og = fast_sig(zo);
    float gg = fast_tanh(zg);
    float cn = fmaf(fg, c_in[idx], ig * gg);
    float hn = og * fast_tanh(cn);
    out[OFF_H + idx] = hn;
    out[OFF_C + idx] = cn;
}

// ---------------------------------------------------------------------------
// Kernel E: mel projection. Grid (B), 96 threads (80 active).
// ---------------------------------------------------------------------------
__global__ void __launch_bounds__(96) mel_proj(
    const float* __restrict__ pw, const float* __restrict__ pb,
    float* __restrict__ out)
{
    const int b = blockIdx.x, j = threadIdx.x;
    if (j >= MELD) return;
    const float* hn = out + OFF_H + b*DECD;
    float a0 = 0.f, a1 = 0.f, a2 = 0.f, a3 = 0.f;
    for (int k = 0; k < DECD; k += 4) {
        a0 = fmaf(hn[k  ], pw[(k  )*MELD + j], a0);
        a1 = fmaf(hn[k+1], pw[(k+1)*MELD + j], a1);
        a2 = fmaf(hn[k+2], pw[(k+2)*MELD + j], a2);
        a3 = fmaf(hn[k+3], pw[(k+3)*MELD + j], a3);
    }
    out[OFF_MEL + b*MELD + j] = (a0 + a1) + (a2 + a3) + pb[j];
}

// ---------------------------------------------------------------------------
extern "C" void kernel_launch(void* const* d_in, const int* in_sizes, int n_in,
                              void* d_out, int out_size)
{
    const float* pm    = (const float*)d_in[0];  // prev_mel_frame [32,80]
    const float* enc   = (const float*)d_in[1];  // encoder_outputs [32,1024,1024]
    const float* h     = (const float*)d_in[2];  // h [32,1024]
    const float* c     = (const float*)d_in[3];  // c [32,1024]
    const float* ascl  = (const float*)d_in[4];  // attn_scale [1024]
    const float* Wk    = (const float*)d_in[5];  // kernel [1104,4096]
    const float* Wr    = (const float*)d_in[6];  // rec_kernel [1024,4096]
    const float* bias  = (const float*)d_in[7];  // bias [4096]
    const float* pw    = (const float*)d_in[8];  // proj_w [1024,80]
    const float* pb    = (const float*)d_in[9];  // proj_b [80]
    float* out = (float*)d_out;

    dim3 gA(BB, NC);
    attn_partial<<<gA, 256>>>(enc, h, ascl);
    attn_combine<<<BB, 256>>>();
    dim3 gC(32, KSPLIT);
    lstm_gemm<<<gC, 128>>>(pm, h, Wk, Wr);
    lstm_gates<<<256, 128>>>(c, bias, out);
    mel_proj<<<BB, 96>>>(pw, pb, out);
}

// round 4
// speedup vs baseline: 2.1009x; 1.8150x over previous
#include <cuda_runtime.h>
#include <math.h>

// Problem dims
#define BB    32
#define TENC  1024
#define ENCD  1024
#define DECD  1024
#define MELD  80
// Attention split
#define NC    32          // chunks over T
#define CT    32          // timesteps per chunk
// LSTM GEMM
#define KTOT  2128        // 80 (mel) + 1024 (ctx) + 1024 (h)
#define TK    16
#define NTILES 133        // 2128/16
#define KSPLIT 19
#define TPS    7          // 133/19

// Output layout: [mel(32*80), h_new(32*1024), c_new(32*1024)]
#define OFF_MEL 0
#define OFF_H   (BB*MELD)
#define OFF_C   (BB*MELD + BB*DECD)

// Scratch (static device memory — no allocations allowed)
__device__ float g_m[BB*NC];
__device__ float g_l[BB*NC];
__device__ float g_acc[BB*NC*ENCD];
__device__ float g_ctx[BB*ENCD];
__device__ float g_zp[KSPLIT*BB*4*DECD];

#define LOG2E  1.4426950408889634f
#define LOG2E2 2.8853900817779268f

// HW tanh (MUFU.TANH) — attention scores only; error damped by softmax+GEMM.
__device__ __forceinline__ float tanhA(float x) {
    float y; asm("tanh.approx.f32 %0, %1;" : "=f"(y) : "f"(x)); return y;
}
// Accurate-ish versions for the LSTM gate outputs (written directly to d_out)
__device__ __forceinline__ float fast_tanh(float x) {
    float u = exp2f(x * LOG2E2);
    return 1.0f - __fdividef(2.0f, u + 1.0f);
}
__device__ __forceinline__ float fast_sig(float x) {
    return __fdividef(1.0f, 1.0f + exp2f(-LOG2E * x));
}

// f32x2 packed FMA helpers
typedef unsigned long long u64t;
__device__ __forceinline__ u64t pack2(float w) {
    u64t r; asm("mov.b64 %0, {%1, %1};" : "=l"(r) : "f"(w)); return r;
}
__device__ __forceinline__ void fma2(u64t& a, u64t x, u64t w) {
    asm("fma.rn.f32x2 %0, %1, %2, %0;" : "+l"(a) : "l"(x), "l"(w));
}
__device__ __forceinline__ float2 unpack2(u64t a) {
    float2 f; asm("mov.b64 {%0, %1}, %2;" : "=f"(f.x), "=f"(f.y) : "l"(a)); return f;
}

// ---------------------------------------------------------------------------
// Kernel A: attention chunk partials. Grid (B, NC), 256 threads (8 warps).
// Phase A: warp w computes scores of t = 4w..4w+3 (all warps parallel, no sync).
// Merge (1 warp): chunk-local softmax max/weights/sum.
// Phase B: warp w owns D-slice [128w,128w+128), accumulates float4 per lane
// over all 32 t (rows are L1/L2-hot from phase A).
// Only 2 __syncthreads per CTA. enc read from DRAM exactly once.
// ---------------------------------------------------------------------------
__global__ void __launch_bounds__(256) attn_partial(
    const float* __restrict__ enc, const float* __restrict__ h,
    const float* __restrict__ scale)
{
    const int b = blockIdx.x, c = blockIdx.y;
    const int tid = threadIdx.x;
    const int wid = tid >> 5, lane = tid & 31;

    // Per-lane D-slice for phase A: d4 = lane + 32k, k=0..7
    float4 hs[8], sc[8];
    const float4* h4 = (const float4*)(h + b*DECD);
    const float4* s4 = (const float4*)scale;
    #pragma unroll
    for (int k = 0; k < 8; k++) { hs[k] = h4[lane + 32*k]; sc[k] = s4[lane + 32*k]; }

    __shared__ float s_sm[CT];
    __shared__ float w_sm[CT];

    const float* encb = enc + ((long)(b*TENC) + c*CT)*ENCD;

    // ---- Phase A ----
    #pragma unroll
    for (int i = 0; i < 4; i++) {
        const int t = wid*4 + i;
        const float4* eA = (const float4*)(encb + t*ENCD) + lane;
        float p0 = 0.f, p1 = 0.f, p2 = 0.f, p3 = 0.f;
        #pragma unroll
        for (int k = 0; k < 8; k++) {
            float4 e = eA[32*k];
            p0 = fmaf(sc[k].x, tanhA(hs[k].x + e.x), p0);
            p1 = fmaf(sc[k].y, tanhA(hs[k].y + e.y), p1);
            p2 = fmaf(sc[k].z, tanhA(hs[k].z + e.z), p2);
            p3 = fmaf(sc[k].w, tanhA(hs[k].w + e.w), p3);
        }
        float s = (p0 + p1) + (p2 + p3);
        #pragma unroll
        for (int off = 16; off > 0; off >>= 1)
            s += __shfl_xor_sync(0xffffffffu, s, off);
        if (lane == 0) s_sm[t] = s;
    }
    __syncthreads();

    // ---- Merge: chunk-local softmax (warp 0) ----
    if (wid == 0) {
        float s = s_sm[lane];
        float m = s;
        #pragma unroll
        for (int off = 16; off > 0; off >>= 1)
            m = fmaxf(m, __shfl_xor_sync(0xffffffffu, m, off));
        float wv = exp2f((s - m) * LOG2E);
        float l = wv;
        #pragma unroll
        for (int off = 16; off > 0; off >>= 1)
            l += __shfl_xor_sync(0xffffffffu, l, off);
        w_sm[lane] = wv;
        if (lane == 0) { g_m[b*NC + c] = m; g_l[b*NC + c] = l; }
    }
    __syncthreads();

    // ---- Phase B: weighted accumulate (rows are cache-hot) ----
    const float4* eB = (const float4*)encb + wid*32 + lane;
    float4 acc = make_float4(0.f, 0.f, 0.f, 0.f);
    #pragma unroll 8
    for (int t = 0; t < CT; t++) {
        float wv = w_sm[t];
        float4 v = eB[t*256];
        acc.x = fmaf(wv, v.x, acc.x); acc.y = fmaf(wv, v.y, acc.y);
        acc.z = fmaf(wv, v.z, acc.z); acc.w = fmaf(wv, v.w, acc.w);
    }
    ((float4*)(g_acc + (b*NC + c)*ENCD))[wid*32 + lane] = acc;
}

// ---------------------------------------------------------------------------
// Kernel B: combine chunk partials -> context. Grid (B), 256 threads.
// ---------------------------------------------------------------------------
__global__ void __launch_bounds__(256) attn_combine()
{
    const int b = blockIdx.x, tid = threadIdx.x;
    __shared__ float sm[NC], sl[NC], sf[NC];
    if (tid < NC) { sm[tid] = g_m[b*NC + tid]; sl[tid] = g_l[b*NC + tid]; }
    __syncthreads();
    float M = -INFINITY;
    #pragma unroll
    for (int c = 0; c < NC; c++) M = fmaxf(M, sm[c]);
    if (tid < NC) sf[tid] = exp2f((sm[tid] - M) * LOG2E);
    __syncthreads();
    float L = 0.0f;
    #pragma unroll
    for (int c = 0; c < NC; c++) L += sl[c] * sf[c];
    float invL = __fdividef(1.0f, L);

    const float4* ga = (const float4*)g_acc;
    float4 v = make_float4(0.f, 0.f, 0.f, 0.f);
    #pragma unroll 8
    for (int c = 0; c < NC; c++) {
        float4 a = ga[(b*NC + c)*256 + tid];
        float f = sf[c];
        v.x = fmaf(a.x, f, v.x); v.y = fmaf(a.y, f, v.y);
        v.z = fmaf(a.z, f, v.z); v.w = fmaf(a.w, f, v.w);
    }
    v.x *= invL; v.y *= invL; v.z *= invL; v.w *= invL;
    ((float4*)(g_ctx + b*ENCD))[tid] = v;
}

// ---------------------------------------------------------------------------
// Kernel C: z partials = x@Wk + h@Wr, packed f32x2 FMA.
// Grid (32 j-blocks, KSPLIT=19), 128 threads.
// ---------------------------------------------------------------------------
__global__ void __launch_bounds__(128) lstm_gemm(
    const float* __restrict__ pm, const float* __restrict__ h,
    const float* __restrict__ Wk, const float* __restrict__ Wr)
{
    const int tid = threadIdx.x;
    const int j   = blockIdx.x * 128 + tid;
    const int ks  = blockIdx.y;

    u64t acc2[16];
    #pragma unroll
    for (int i = 0; i < 16; i++) acc2[i] = 0ull;

    __shared__ __align__(16) float xs[TK * 34];   // xs[kk*34 + b]

    const int tile0 = ks * TPS;
    for (int tile = tile0; tile < tile0 + TPS; tile++) {
        const int kbase = tile * TK;
        __syncthreads();
        #pragma unroll
        for (int i = 0; i < 4; i++) {
            int idx = tid + 128*i;        // [0,512)
            int bb  = idx >> 4;
            int kk  = idx & 15;
            int k   = kbase + kk;
            float v;
            if (k < MELD)            v = pm[bb*MELD + k];
            else if (k < MELD+ENCD)  v = g_ctx[bb*ENCD + (k - MELD)];
            else                     v = h[bb*DECD + (k - MELD - ENCD)];
            xs[kk*34 + bb] = v;
        }
        __syncthreads();

        const float* wrow = (tile < 69)
            ? (Wk + (long)kbase*4096 + j)
            : (Wr + (long)(kbase - (MELD+ENCD))*4096 + j);

        #pragma unroll
        for (int kk = 0; kk < TK; kk++) {
            u64t w2 = pack2(wrow[kk*4096]);
            const u64t* xp = reinterpret_cast<const u64t*>(xs + kk*34);
            #pragma unroll
            for (int bb = 0; bb < 16; bb++)
                fma2(acc2[bb], xp[bb], w2);
        }
    }
    #pragma unroll
    for (int bb = 0; bb < 16; bb++) {
        float2 f = unpack2(acc2[bb]);
        g_zp[(ks*32 + 2*bb  )*4*DECD + j] = f.x;
        g_zp[(ks*32 + 2*bb+1)*4*DECD + j] = f.y;
    }
}

// ---------------------------------------------------------------------------
// Kernel D: sum K-split partials + bias, gates, write h_new/c_new.
// Grid 256 x 128 threads -> 32768 = B*DEC elements.
// ---------------------------------------------------------------------------
__global__ void __launch_bounds__(128) lstm_gates(
    const float* __restrict__ c_in, const float* __restrict__ bias,
    float* __restrict__ out)
{
    const int idx = blockIdx.x*128 + threadIdx.x;   // [0, 32768)
    const int b = idx >> 10, jj = idx & 1023;

    float zi = bias[jj], zf = bias[DECD + jj];
    float zg = bias[2*DECD + jj], zo = bias[3*DECD + jj];
    #pragma unroll
    for (int ks = 0; ks < KSPLIT; ks++) {
        const float* zp = g_zp + (ks*32 + b)*4*DECD;
        zi += zp[jj];
        zf += zp[DECD + jj];
        zg += zp[2*DECD + jj];
        zo += zp[3*DECD + jj];
    }
    float ig = fast_sig(zi), fg = fast_sig(zf), og = fast_sig(zo);
    float gg = fast_tanh(zg);
    float cn = fmaf(fg, c_in[idx], ig * gg);
    float hn = og * fast_tanh(cn);
    out[OFF_H + idx] = hn;
    out[OFF_C + idx] = cn;
}

// ---------------------------------------------------------------------------
// Kernel E: mel projection. Grid (B), block (96, 4): 4-way k-split + smem
// reduce. j in [0,80), slice ty covers k = ty*256 .. ty*256+255.
// ---------------------------------------------------------------------------
__global__ void __launch_bounds__(384) mel_proj(
    const float* __restrict__ pw, const float* __restrict__ pb,
    float* __restrict__ out)
{
    const int b = blockIdx.x;
    const int j = threadIdx.x;          // 0..95 (80 active)
    const int ty = threadIdx.y;         // 0..3
    __shared__ float red[4][96];

    float a0 = 0.f, a1 = 0.f, a2 = 0.f, a3 = 0.f;
    if (j < MELD) {
        const float* hn = out + OFF_H + b*DECD + ty*256;
        const float* pwk = pw + (long)(ty*256)*MELD + j;
        #pragma unroll 4
        for (int k = 0; k < 256; k += 4) {
            a0 = fmaf(hn[k  ], pwk[(k  )*MELD], a0);
            a1 = fmaf(hn[k+1], pwk[(k+1)*MELD], a1);
            a2 = fmaf(hn[k+2], pwk[(k+2)*MELD], a2);
            a3 = fmaf(hn[k+3], pwk[(k+3)*MELD], a3);
        }
    }
    red[ty][j] = (a0 + a1) + (a2 + a3);
    __syncthreads();
    if (ty == 0 && j < MELD) {
        out[OFF_MEL + b*MELD + j] =
            red[0][j] + red[1][j] + red[2][j] + red[3][j] + pb[j];
    }
}

// ---------------------------------------------------------------------------
extern "C" void kernel_launch(void* const* d_in, const int* in_sizes, int n_in,
                              void* d_out, int out_size)
{
    const float* pm    = (const float*)d_in[0];  // prev_mel_frame [32,80]
    const float* enc   = (const float*)d_in[1];  // encoder_outputs [32,1024,1024]
    const float* h     = (const float*)d_in[2];  // h [32,1024]
    const float* c     = (const float*)d_in[3];  // c [32,1024]
    const float* ascl  = (const float*)d_in[4];  // attn_scale [1024]
    const float* Wk    = (const float*)d_in[5];  // kernel [1104,4096]
    const float* Wr    = (const float*)d_in[6];  // rec_kernel [1024,4096]
    const float* bias  = (const float*)d_in[7];  // bias [4096]
    const float* pw    = (const float*)d_in[8];  // proj_w [1024,80]
    const float* pb    = (const float*)d_in[9];  // proj_b [80]
    float* out = (float*)d_out;

    dim3 gA(BB, NC);
    attn_partial<<<gA, 256>>>(enc, h, ascl);
    attn_combine<<<BB, 256>>>();
    dim3 gC(32, KSPLIT);
    lstm_gemm<<<gC, 128>>>(pm, h, Wk, Wr);
    lstm_gates<<<256, 128>>>(c, bias, out);
    dim3 bE(96, 4);
    mel_proj<<<BB, bE>>>(pw, pb, out);
}